// round 4
// baseline (speedup 1.0000x reference)
#include <cuda_runtime.h>
#include <cuda_fp16.h>

// PairwisePotential1 — 4 px/thread, f32x2 packed arithmetic + f16x2 EX2.
// out = w1 * first/9 + w2 * (4+4*sqrt2)/9
// first = 1 + sum_{8 offsets} exp2(K*diff^2 + K*d),  K = -0.5*log2(e).
// Window rows y-1..y+1, cols x-1..x+1 (forward-rooted), zero padding.

#define S 128
#define SS (S * S)

typedef unsigned long long u64;

__device__ __forceinline__ u64 pk(float lo, float hi) {
    u64 r; asm("mov.b64 %0, {%1, %2};" : "=l"(r) : "f"(lo), "f"(hi)); return r;
}
__device__ __forceinline__ void upk(u64 v, float& lo, float& hi) {
    asm("mov.b64 {%0, %1}, %2;" : "=f"(lo), "=f"(hi) : "l"(v));
}
__device__ __forceinline__ u64 fma2(u64 a, u64 b, u64 c) {
    u64 r; asm("fma.rn.f32x2 %0, %1, %2, %3;" : "=l"(r) : "l"(a), "l"(b), "l"(c)); return r;
}
__device__ __forceinline__ u64 mul2(u64 a, u64 b) {
    u64 r; asm("mul.rn.f32x2 %0, %1, %2;" : "=l"(r) : "l"(a), "l"(b)); return r;
}
__device__ __forceinline__ u64 add2(u64 a, u64 b) {
    u64 r; asm("add.rn.f32x2 %0, %1, %2;" : "=l"(r) : "l"(a), "l"(b)); return r;
}

__global__ __launch_bounds__(256) void pp_kernel(
    const float* __restrict__ x,
    const float* __restrict__ w1,
    const float* __restrict__ w2,
    float* __restrict__ out)
{
    int t  = blockIdx.x * blockDim.x + threadIdx.x;  // one thread = 4 consecutive x
    int xq = (t & 31) << 2;            // 0,4,...,124
    int y  = (t >> 5) & (S - 1);
    int bc = t >> 12;                  // b*C + c
    int c  = bc & 63;

    const float* __restrict__ xb = x + (size_t)bc * SS;

    // rows y-1, y, y+1 ; columns xq-1 .. xq+4  (6 values per row), zero OOB
    float r[3][6];
#pragma unroll
    for (int i = 0; i < 3; i++) {
        int ry = y - 1 + i;
        bool okY = (ry >= 0) & (ry < S);
        const float* __restrict__ row = xb + ry * S;
        float4 m = okY ? *(const float4*)(row + xq) : make_float4(0.f, 0.f, 0.f, 0.f);
        r[i][1] = m.x; r[i][2] = m.y; r[i][3] = m.z; r[i][4] = m.w;
        r[i][0] = (okY & (xq > 0))     ? __ldg(row + xq - 1) : 0.f;
        r[i][5] = (okY & (xq + 4 < S)) ? __ldg(row + xq + 4) : 0.f;
    }

    const float Kf  = -0.5f * 1.44269504088896340736f;  // -0.5*log2(e)
    const u64 K2   = pk(Kf, Kf);
    const u64 LL1  = pk(Kf, Kf);                                // d = 1 offset
    const float L2f = Kf * 1.41421356237309504880f;
    const u64 LL2  = pk(L2f, L2f);                              // d = sqrt(2) offset
    const u64 NEG1 = pk(-1.0f, -1.0f);
    const u64 ONE2 = pk(1.0f, 1.0f);

    const float INV9   = 1.0f / 9.0f;
    const float SECOND = (4.0f + 4.0f * 1.41421356237309504880f) / 9.0f;
    const u64 INV9_2 = pk(INV9, INV9);
    const u64 SEC2   = pk(SECOND, SECOND);

    int wbase = c * SS + y * S + xq;
    float4 w1v = *(const float4*)(w1 + wbase);
    float4 w2v = *(const float4*)(w2 + wbase);

    float o[4];
#pragma unroll
    for (int q = 0; q < 2; q++) {        // pixel pair (p, p+1), p = 2q
        const int p = 2 * q;
        const u64 cv = pk(r[0][p], r[0][p + 1]);

        __half2 accA = __float2half2_rn(0.0f);   // d = 1 terms
        __half2 accB = __float2half2_rn(0.0f);   // d = sqrt(2) terms

#define TERM(nlo, nhi, LL, ACC) {                          \
        u64 d_  = fma2(pk((nlo), (nhi)), NEG1, cv);        \
        u64 s_  = mul2(d_, d_);                            \
        u64 a_  = fma2(s_, K2, LL);                        \
        float alo_, ahi_; upk(a_, alo_, ahi_);             \
        __half2 h_ = __floats2half2_rn(alo_, ahi_);        \
        ACC = __hadd2(ACC, h2exp2(h_)); }

        // d = 1 terms: neighbors r[0][p+1], r[0][p+2], r[1][p], r[2][p]
        TERM(r[0][p + 1], r[0][p + 2], LL1, accA)
        TERM(r[0][p + 2], r[0][p + 3], LL1, accA)
        TERM(r[1][p],     r[1][p + 1], LL1, accA)
        TERM(r[2][p],     r[2][p + 1], LL1, accA)
        // d = sqrt(2) terms: r[1][p+1], r[1][p+2], r[2][p+1], r[2][p+2]
        TERM(r[1][p + 1], r[1][p + 2], LL2, accB)
        TERM(r[1][p + 2], r[1][p + 3], LL2, accB)
        TERM(r[2][p + 1], r[2][p + 2], LL2, accB)
        TERM(r[2][p + 2], r[2][p + 3], LL2, accB)
#undef TERM

        float2 fA = __half22float2(accA);
        float2 fB = __half22float2(accB);
        u64 first = add2(add2(pk(fA.x, fA.y), pk(fB.x, fB.y)), ONE2);

        u64 w1p = q ? pk(w1v.z, w1v.w) : pk(w1v.x, w1v.y);
        u64 w2p = q ? pk(w2v.z, w2v.w) : pk(w2v.x, w2v.y);
        u64 res = fma2(w1p, mul2(first, INV9_2), mul2(w2p, SEC2));
        upk(res, o[p], o[p + 1]);
    }

    ((float4*)out)[t] = make_float4(o[0], o[1], o[2], o[3]);
}

extern "C" void kernel_launch(void* const* d_in, const int* in_sizes, int n_in,
                              void* d_out, int out_size)
{
    const float* x  = (const float*)d_in[0];
    const float* w1 = (const float*)d_in[1];
    const float* w2 = (const float*)d_in[2];
    float* out = (float*)d_out;

    int total4 = out_size >> 2;          // 4 pixels per thread
    int threads = 256;
    int blocks = (total4 + threads - 1) / threads;
    pp_kernel<<<blocks, threads>>>(x, w1, w2, out);
}

// round 5
// speedup vs baseline: 1.0250x; 1.0250x over previous
#include <cuda_runtime.h>
#include <cuda_fp16.h>

// PairwisePotential1 — 8 px/thread, f32x2 packed math + f16x2 EX2.
// out = w1 * first/9 + w2 * (4+4*sqrt2)/9
// first = 1 + sum_{8 offsets} exp2(K*diff^2 + K*d),  K = -0.5*log2(e).
// Window rows y-1..y+1, cols x-1..x+1 (forward-rooted), zero padding.
// Pixel pairs (2q, 2q+1): pairs with odd v-index start alias float4 lane
// pairs (zero-cost packs); misaligned packs cost 2 MOVs each.

#define S 128
#define SS (S * S)

typedef unsigned long long u64;

__device__ __forceinline__ u64 pk(float lo, float hi) {
    u64 r; asm("mov.b64 %0, {%1, %2};" : "=l"(r) : "f"(lo), "f"(hi)); return r;
}
__device__ __forceinline__ void upk(u64 v, float& lo, float& hi) {
    asm("mov.b64 {%0, %1}, %2;" : "=f"(lo), "=f"(hi) : "l"(v));
}
__device__ __forceinline__ u64 fma2(u64 a, u64 b, u64 c) {
    u64 r; asm("fma.rn.f32x2 %0, %1, %2, %3;" : "=l"(r) : "l"(a), "l"(b), "l"(c)); return r;
}
__device__ __forceinline__ u64 mul2(u64 a, u64 b) {
    u64 r; asm("mul.rn.f32x2 %0, %1, %2;" : "=l"(r) : "l"(a), "l"(b)); return r;
}
__device__ __forceinline__ u64 add2(u64 a, u64 b) {
    u64 r; asm("add.rn.f32x2 %0, %1, %2;" : "=l"(r) : "l"(a), "l"(b)); return r;
}

__global__ __launch_bounds__(256) void pp_kernel(
    const float* __restrict__ x,
    const float* __restrict__ w1,
    const float* __restrict__ w2,
    float* __restrict__ out)
{
    int t  = blockIdx.x * blockDim.x + threadIdx.x;  // one thread = 8 consecutive x
    int xo = (t & 15) << 3;            // 0,8,...,120
    int y  = (t >> 4) & (S - 1);
    int bc = t >> 11;                  // b*C + c
    int c  = bc & 63;

    const float* __restrict__ xb = x + (size_t)bc * SS;

    // v[i][k] = x(row y-1+i, col xo-1+k), k = 0..9, zero OOB.
    // v[i][1..4] and v[i][5..8] come from two float4 loads.
    float v[3][10];
#pragma unroll
    for (int i = 0; i < 3; i++) {
        int ry = y - 1 + i;
        bool okY = (ry >= 0) & (ry < S);
        const float* __restrict__ rp = xb + ry * S + xo;
        float4 A = okY ? *(const float4*)(rp)     : make_float4(0.f, 0.f, 0.f, 0.f);
        float4 B = okY ? *(const float4*)(rp + 4) : make_float4(0.f, 0.f, 0.f, 0.f);
        v[i][0] = (okY & (xo > 0))     ? __ldg(rp - 1) : 0.f;
        v[i][1] = A.x; v[i][2] = A.y; v[i][3] = A.z; v[i][4] = A.w;
        v[i][5] = B.x; v[i][6] = B.y; v[i][7] = B.z; v[i][8] = B.w;
        v[i][9] = (okY & (xo + 8 < S)) ? __ldg(rp + 8) : 0.f;
    }

    const float Kf  = -0.5f * 1.44269504088896340736f;   // -0.5*log2(e)
    const u64 K2   = pk(Kf, Kf);
    const u64 LL1  = pk(Kf, Kf);                          // d = 1
    const float L2f = Kf * 1.41421356237309504880f;
    const u64 LL2  = pk(L2f, L2f);                        // d = sqrt(2)
    const u64 NEG1 = pk(-1.0f, -1.0f);

    const float INV9   = 1.0f / 9.0f;
    const float SECOND = (4.0f + 4.0f * 1.41421356237309504880f) / 9.0f;
    const u64 INV9_2 = pk(INV9, INV9);
    const u64 SEC2   = pk(SECOND, SECOND);

    int wbase = c * SS + y * S + xo;
    float4 w1a = *(const float4*)(w1 + wbase);
    float4 w1b = *(const float4*)(w1 + wbase + 4);
    float4 w2a = *(const float4*)(w2 + wbase);
    float4 w2b = *(const float4*)(w2 + wbase + 4);

    float o[8];
#pragma unroll
    for (int q = 0; q < 4; q++) {        // pixel pair (p, p+1)
        const int p = 2 * q;
        // centers: columns xo+p-1, xo+p  ->  v[0][p], v[0][p+1]
        const u64 cv = pk(v[0][p], v[0][p + 1]);

        __half2 accA = __float2half2_rn(1.0f);   // d=1 terms, self term folded in
        __half2 accB = __float2half2_rn(0.0f);   // d=sqrt(2) terms

#define TERM(nlo, nhi, LL, ACC) {                          \
        u64 d_  = fma2(pk((nlo), (nhi)), NEG1, cv);        \
        u64 s_  = mul2(d_, d_);                            \
        u64 a_  = fma2(s_, K2, LL);                        \
        float alo_, ahi_; upk(a_, alo_, ahi_);             \
        __half2 h_ = __floats2half2_rn(alo_, ahi_);        \
        ACC = __hadd2(ACC, h2exp2(h_)); }

        // d = 1: (0,1) (0,2) (1,0) (2,0)
        TERM(v[0][p + 1], v[0][p + 2], LL1, accA)   // aligned pack (p+1 odd)
        TERM(v[0][p + 2], v[0][p + 3], LL1, accA)
        TERM(v[1][p],     v[1][p + 1], LL1, accA)
        TERM(v[2][p],     v[2][p + 1], LL1, accA)
        // d = sqrt(2): (1,1) (1,2) (2,1) (2,2)
        TERM(v[1][p + 1], v[1][p + 2], LL2, accB)   // aligned
        TERM(v[1][p + 2], v[1][p + 3], LL2, accB)
        TERM(v[2][p + 1], v[2][p + 2], LL2, accB)   // aligned
        TERM(v[2][p + 2], v[2][p + 3], LL2, accB)
#undef TERM

        float2 fA = __half22float2(accA);
        float2 fB = __half22float2(accB);
        u64 first = add2(pk(fA.x, fA.y), pk(fB.x, fB.y));  // includes the +1

        u64 w1p = (q == 0) ? pk(w1a.x, w1a.y) : (q == 1) ? pk(w1a.z, w1a.w)
                : (q == 2) ? pk(w1b.x, w1b.y) : pk(w1b.z, w1b.w);
        u64 w2p = (q == 0) ? pk(w2a.x, w2a.y) : (q == 1) ? pk(w2a.z, w2a.w)
                : (q == 2) ? pk(w2b.x, w2b.y) : pk(w2b.z, w2b.w);
        u64 res = fma2(w1p, mul2(first, INV9_2), mul2(w2p, SEC2));
        upk(res, o[p], o[p + 1]);
    }

    float4* op = (float4*)(out + (size_t)t * 8);
    op[0] = make_float4(o[0], o[1], o[2], o[3]);
    op[1] = make_float4(o[4], o[5], o[6], o[7]);
}

extern "C" void kernel_launch(void* const* d_in, const int* in_sizes, int n_in,
                              void* d_out, int out_size)
{
    const float* x  = (const float*)d_in[0];
    const float* w1 = (const float*)d_in[1];
    const float* w2 = (const float*)d_in[2];
    float* out = (float*)d_out;

    int total8 = out_size >> 3;          // 8 pixels per thread
    int threads = 256;
    int blocks = (total8 + threads - 1) / threads;
    pp_kernel<<<blocks, threads>>>(x, w1, w2, out);
}

// round 6
// speedup vs baseline: 1.0732x; 1.0470x over previous
#include <cuda_runtime.h>
#include <cuda_fp16.h>

// PairwisePotential1 — 4 px/thread, half2 window math + f16x2 EX2.
// out = w1 * first/9 + w2 * (4+4*sqrt2)/9
// first = 1 + sum_{8 offsets} exp2(K*diff^2 + K*d),  K = -0.5*log2(e).
// Window rows y-1..y+1, cols x-1..x+1 (forward-rooted), zero padding.
//
// Pixel pairs are packed into half2 lanes. cvt.rn.f16x2.f32 (F2FP) packs two
// arbitrary f32 regs in one instruction, so pair construction is free —
// this removes the mov.b64 pack tax that sank the f32x2 variants.

#define S 128
#define SS (S * S)

__global__ __launch_bounds__(256) void pp_kernel(
    const float* __restrict__ x,
    const float* __restrict__ w1,
    const float* __restrict__ w2,
    float* __restrict__ out)
{
    int t  = blockIdx.x * blockDim.x + threadIdx.x;  // one thread = 4 consecutive x
    int xq = (t & 31) << 2;            // 0,4,...,124
    int y  = (t >> 5) & (S - 1);
    int bc = t >> 12;                  // b*C + c
    int c  = bc & 63;

    const float* __restrict__ xb = x + (size_t)bc * SS;

    // rows y-1, y, y+1 ; columns xq-1 .. xq+4  (6 values per row), zero OOB
    float r0[6], r1[6], r2[6];
    {
        float* rr[3] = { r0, r1, r2 };
#pragma unroll
        for (int i = 0; i < 3; i++) {
            int ry = y - 1 + i;
            bool okY = (ry >= 0) & (ry < S);
            const float* __restrict__ row = xb + ry * S;
            float4 m = okY ? *(const float4*)(row + xq) : make_float4(0.f, 0.f, 0.f, 0.f);
            rr[i][1] = m.x; rr[i][2] = m.y; rr[i][3] = m.z; rr[i][4] = m.w;
            rr[i][0] = (okY & (xq > 0))     ? __ldg(row + xq - 1) : 0.f;
            rr[i][5] = (okY & (xq + 4 < S)) ? __ldg(row + xq + 4) : 0.f;
        }
    }

    // half2 sliding pairs: h{row}[k] = (v[k], v[k+1]), k = 0..4.  One F2FP each.
    __half2 h0[5], h1[5], h2[5];
#pragma unroll
    for (int k = 0; k < 5; k++) {
        h0[k] = __floats2half2_rn(r0[k], r0[k + 1]);
        h1[k] = __floats2half2_rn(r1[k], r1[k + 1]);
        h2[k] = __floats2half2_rn(r2[k], r2[k + 1]);
    }

    const float Kf  = -0.5f * 1.44269504088896340736f;   // -0.5*log2(e)
    const __half2 K2h = __float2half2_rn(Kf);
    const __half2 L1h = __float2half2_rn(Kf);                          // d = 1
    const __half2 L2h = __float2half2_rn(Kf * 1.41421356237309504880f); // d = sqrt(2)

    const float INV9   = 1.0f / 9.0f;
    const float SECOND = (4.0f + 4.0f * 1.41421356237309504880f) / 9.0f;

    int wbase = c * SS + y * S + xq;
    float4 w1v = *(const float4*)(w1 + wbase);
    float4 w2v = *(const float4*)(w2 + wbase);

    float first[4];
#pragma unroll
    for (int q = 0; q < 2; q++) {        // pixel pair (p, p+1)
        const int p = 2 * q;
        const __half2 cv = h0[p];        // centers (v0[p], v0[p+1])

        __half2 accA = __float2half2_rn(1.0f);   // d=1 terms + self term
        __half2 accB = __float2half2_rn(0.0f);   // d=sqrt(2) terms

#define TERM(N, LL, ACC) {                         \
        __half2 d_ = __hsub2(cv, (N));             \
        __half2 t_ = __hmul2(d_, K2h);             \
        __half2 a_ = __hfma2(t_, d_, (LL));        \
        ACC = __hadd2(ACC, h2exp2(a_)); }

        // d = 1: offsets (0,1) (0,2) (1,0) (2,0)
        TERM(h0[p + 1], L1h, accA)
        TERM(h0[p + 2], L1h, accA)
        TERM(h1[p],     L1h, accA)
        TERM(h2[p],     L1h, accA)
        // d = sqrt(2): offsets (1,1) (1,2) (2,1) (2,2)
        TERM(h1[p + 1], L2h, accB)
        TERM(h1[p + 2], L2h, accB)
        TERM(h2[p + 1], L2h, accB)
        TERM(h2[p + 2], L2h, accB)
#undef TERM

        float2 fA = __half22float2(accA);
        float2 fB = __half22float2(accB);
        first[p]     = fA.x + fB.x;
        first[p + 1] = fA.y + fB.y;
    }

    float4 o;
    o.x = fmaf(w1v.x, first[0] * INV9, w2v.x * SECOND);
    o.y = fmaf(w1v.y, first[1] * INV9, w2v.y * SECOND);
    o.z = fmaf(w1v.z, first[2] * INV9, w2v.z * SECOND);
    o.w = fmaf(w1v.w, first[3] * INV9, w2v.w * SECOND);

    ((float4*)out)[t] = o;
}

extern "C" void kernel_launch(void* const* d_in, const int* in_sizes, int n_in,
                              void* d_out, int out_size)
{
    const float* x  = (const float*)d_in[0];
    const float* w1 = (const float*)d_in[1];
    const float* w2 = (const float*)d_in[2];
    float* out = (float*)d_out;

    int total4 = out_size >> 2;          // 4 pixels per thread
    int threads = 256;
    int blocks = (total4 + threads - 1) / threads;
    pp_kernel<<<blocks, threads>>>(x, w1, w2, out);
}